// round 5
// baseline (speedup 1.0000x reference)
#include <cuda_runtime.h>

#define NMAX 8192

// Scratch — zero-initialized at module load; finalize_kernel restores zeros
// after every call so graph replays see a clean state.
__device__ int      g_cntpack[2][NMAX];   // low 16: cnt, high 16: pos_cnt
__device__ float    g_sumexp[2][NMAX];    // sum of exp(out[i]) over mask
__device__ float    g_poslog[2][NMAX];    // sum of out[i] over mask & pos
__device__ float    g_res;                // cross-block partial sum
__device__ unsigned g_done;               // block-completion counter

// Row-major coalesced scan of the full adjacency matrix, int4 vectorized,
// unrolled x4 with front-batched loads for MLP=4. Hits (nonzero, off-diagonal)
// scatter into per-(side, column) accumulators via atomics.
__global__ void __launch_bounds__(256) main_kernel(
    const int4* __restrict__ adj,
    const float* __restrict__ outs,
    const int* __restrict__ tgt,
    int N, int rowShift)
{
    const long long total  = ((long long)N * N) >> 2;          // int4 quads
    const long long stride = (long long)gridDim.x * blockDim.x;
    long long q = (long long)blockIdx.x * blockDim.x + threadIdx.x;

    // Unrolled body: 4 independent loads issued up front.
    for (; q + 3 * stride < total; q += 4 * stride) {
        int4 v0 = __ldg(&adj[q]);
        int4 v1 = __ldg(&adj[q + stride]);
        int4 v2 = __ldg(&adj[q + 2 * stride]);
        int4 v3 = __ldg(&adj[q + 3 * stride]);

        #pragma unroll
        for (int g = 0; g < 4; g++) {
            int4 v = (g == 0) ? v0 : (g == 1) ? v1 : (g == 2) ? v2 : v3;
            if ((v.x | v.y | v.z | v.w) == 0) continue;        // ~98.5% of quads

            long long qq = q + (long long)g * stride;
            int i = (int)(qq >> rowShift);                          // row
            int c = ((int)(qq - ((long long)i << rowShift))) << 2;  // first col of quad

            float o = __ldg(&outs[i]);
            int   p = (__ldg(&tgt[i]) != 0) ? 1 : 0;
            float e = expf(o);
            int   pack = 1 + (p << 16);

            #pragma unroll
            for (int u = 0; u < 4; u++) {
                int val = (u == 0) ? v.x : (u == 1) ? v.y : (u == 2) ? v.z : v.w;
                int cc = c + u;
                if (val != 0 && cc != i) {
                    int side = (i < cc) ? 0 : 1;   // 0 = lower (i < k), 1 = upper
                    atomicAdd(&g_cntpack[side][cc], pack);
                    atomicAdd(&g_sumexp[side][cc], e);
                    if (p) atomicAdd(&g_poslog[side][cc], o);
                }
            }
        }
    }
    // Tail (never taken when stride divides total; kept for generality).
    for (; q < total; q += stride) {
        int4 v = __ldg(&adj[q]);
        if ((v.x | v.y | v.z | v.w) == 0) continue;
        int i = (int)(q >> rowShift);
        int c = ((int)(q - ((long long)i << rowShift))) << 2;
        float o = __ldg(&outs[i]);
        int   p = (__ldg(&tgt[i]) != 0) ? 1 : 0;
        float e = expf(o);
        int   pack = 1 + (p << 16);
        #pragma unroll
        for (int u = 0; u < 4; u++) {
            int val = (u == 0) ? v.x : (u == 1) ? v.y : (u == 2) ? v.z : v.w;
            int cc = c + u;
            if (val != 0 && cc != i) {
                int side = (i < cc) ? 0 : 1;
                atomicAdd(&g_cntpack[side][cc], pack);
                atomicAdd(&g_sumexp[side][cc], e);
                if (p) atomicAdd(&g_poslog[side][cc], o);
            }
        }
    }
}

// One thread per column. Multiplicity comes from a binary search of sorted
// idx_node. Self-cleans all scratch, elects the last block to write out[0].
__global__ void __launch_bounds__(256) finalize_kernel(
    float* __restrict__ out,
    const int* __restrict__ idx,
    int N, int K)
{
    int c = blockIdx.x * blockDim.x + threadIdx.x;
    float local = 0.f;

    if (c < N) {
        // lower_bound(c)
        int lo = 0, hi = K;
        while (lo < hi) { int mid = (lo + hi) >> 1; if (__ldg(&idx[mid]) < c) lo = mid + 1; else hi = mid; }
        int lb = lo;
        // upper_bound(c)
        hi = K;
        while (lo < hi) { int mid = (lo + hi) >> 1; if (__ldg(&idx[mid]) <= c) lo = mid + 1; else hi = mid; }
        int m = lo - lb;   // multiplicity of column c in idx_node

        if (m > 0) {
            int   pack0 = g_cntpack[0][c], pack1 = g_cntpack[1][c];
            float se0 = g_sumexp[0][c], se1 = g_sumexp[1][c];
            float pl0 = g_poslog[0][c], pl1 = g_poslog[1][c];
            int cnt0 = pack0 & 0xFFFF, pc0 = pack0 >> 16;
            int cnt1 = pack1 & 0xFFFF, pc1 = pack1 >> 16;
            if (cnt0 > 0 && pc0 == 1) local += (float)m * (logf(se0) - pl0) / (float)cnt0;
            if (cnt1 > 0 && pc1 == 1) local += (float)m * (logf(se1) - pl1) / (float)cnt1;
        }
        // Self-clean for the next graph replay.
        g_cntpack[0][c] = 0; g_cntpack[1][c] = 0;
        g_sumexp[0][c] = 0.f; g_sumexp[1][c] = 0.f;
        g_poslog[0][c] = 0.f; g_poslog[1][c] = 0.f;
    }

    // Warp reduce, then block reduce in shared memory.
    #pragma unroll
    for (int s = 16; s > 0; s >>= 1)
        local += __shfl_xor_sync(0xFFFFFFFF, local, s);

    __shared__ float warpsum[8];
    int lane = threadIdx.x & 31, wid = threadIdx.x >> 5;
    if (lane == 0) warpsum[wid] = local;
    __syncthreads();
    if (wid == 0) {
        float b = (lane < 8) ? warpsum[lane] : 0.f;
        #pragma unroll
        for (int s = 4; s > 0; s >>= 1)
            b += __shfl_xor_sync(0xFFFFFFFF, b, s);
        if (lane == 0) {
            atomicAdd(&g_res, b);
            __threadfence();
            unsigned t = atomicAdd(&g_done, 1u);
            if (t == gridDim.x - 1) {
                // Last block: publish result, reset scratch for next replay.
                out[0] = atomicExch(&g_res, 0.f);
                g_done = 0;
            }
        }
    }
}

extern "C" void kernel_launch(void* const* d_in, const int* in_sizes, int n_in,
                              void* d_out, int out_size) {
    const float* outs = (const float*)d_in[0];   // outputs  [N] f32
    const int*   tgt  = (const int*)d_in[1];     // targets  [N] i32
    const int*   adj  = (const int*)d_in[2];     // node_adj [N,N] i32
    const int*   idx  = (const int*)d_in[3];     // idx_node [K] i32 (sorted)
    int N = in_sizes[0];
    int K = in_sizes[3];
    float* out = (float*)d_out;

    // quadsPerRow = N/4 is a power of two; rowShift = log2(N/4)
    int rowShift = 0;
    for (int t = N >> 2; t > 1; t >>= 1) rowShift++;

    // 2048 blocks x 256 threads: stride = 2^19 divides 2^24 quads exactly
    // -> 8 uniform unrolled iterations per thread, zero tail.
    main_kernel<<<2048, 256>>>((const int4*)adj, outs, tgt, N, rowShift);
    finalize_kernel<<<(N + 255) / 256, 256>>>(out, idx, N, K);
}

// round 6
// speedup vs baseline: 1.0741x; 1.0741x over previous
#include <cuda_runtime.h>

#define NMAX 8192

// Scratch — zero-initialized at module load; reduce_kernel restores accumulator
// zeros after every call so graph replays see a clean state. g_contrib is
// overwritten every call, never cleaned.
__device__ int      g_cntpack[2][NMAX];   // low 16: cnt, high 16: pos_cnt
__device__ float    g_sumexp[2][NMAX];    // sum of exp(out[i]) over mask
__device__ float    g_poslog[2][NMAX];    // sum of out[i] over mask & pos
__device__ float    g_contrib[NMAX];      // per-column contribution (overwritten)
__device__ float    g_res;                // cross-block partial sum
__device__ unsigned g_done;               // block-completion counter

// Row-major coalesced scan of the full adjacency matrix, int4 vectorized,
// unrolled x8 with front-batched loads for MLP=8. Hits (nonzero, off-diagonal)
// scatter into per-(side, column) accumulators via atomics.
__global__ void __launch_bounds__(256) main_kernel(
    const int4* __restrict__ adj,
    const float* __restrict__ outs,
    const int* __restrict__ tgt,
    int N, int rowShift)
{
    const long long total  = ((long long)N * N) >> 2;          // int4 quads
    const long long stride = (long long)gridDim.x * blockDim.x;
    long long q = (long long)blockIdx.x * blockDim.x + threadIdx.x;

    for (; q + 7 * stride < total; q += 8 * stride) {
        int4 vv[8];
        #pragma unroll
        for (int g = 0; g < 8; g++)
            vv[g] = __ldg(&adj[q + (long long)g * stride]);

        #pragma unroll
        for (int g = 0; g < 8; g++) {
            int4 v = vv[g];
            if ((v.x | v.y | v.z | v.w) == 0) continue;        // ~98.5% of quads

            long long qq = q + (long long)g * stride;
            int i = (int)(qq >> rowShift);                          // row
            int c = ((int)(qq - ((long long)i << rowShift))) << 2;  // first col of quad

            float o = __ldg(&outs[i]);
            int   p = (__ldg(&tgt[i]) != 0) ? 1 : 0;
            float e = expf(o);
            int   pack = 1 + (p << 16);

            #pragma unroll
            for (int u = 0; u < 4; u++) {
                int val = (u == 0) ? v.x : (u == 1) ? v.y : (u == 2) ? v.z : v.w;
                int cc = c + u;
                if (val != 0 && cc != i) {
                    int side = (i < cc) ? 0 : 1;   // 0 = lower (i < k), 1 = upper
                    atomicAdd(&g_cntpack[side][cc], pack);
                    atomicAdd(&g_sumexp[side][cc], e);
                    if (p) atomicAdd(&g_poslog[side][cc], o);
                }
            }
        }
    }
    // Tail (never taken when stride divides total; kept for generality).
    for (; q < total; q += stride) {
        int4 v = __ldg(&adj[q]);
        if ((v.x | v.y | v.z | v.w) == 0) continue;
        int i = (int)(q >> rowShift);
        int c = ((int)(q - ((long long)i << rowShift))) << 2;
        float o = __ldg(&outs[i]);
        int   p = (__ldg(&tgt[i]) != 0) ? 1 : 0;
        float e = expf(o);
        int   pack = 1 + (p << 16);
        #pragma unroll
        for (int u = 0; u < 4; u++) {
            int val = (u == 0) ? v.x : (u == 1) ? v.y : (u == 2) ? v.z : v.w;
            int cc = c + u;
            if (val != 0 && cc != i) {
                int side = (i < cc) ? 0 : 1;
                atomicAdd(&g_cntpack[side][cc], pack);
                atomicAdd(&g_sumexp[side][cc], e);
                if (p) atomicAdd(&g_poslog[side][cc], o);
            }
        }
    }
}

// Per-column contribution: 6 independent loads, compute, overwrite g_contrib[c].
// No search, no clean, no reduction — single memory round-trip.
__global__ void __launch_bounds__(256) contrib_kernel(int N) {
    int c = blockIdx.x * blockDim.x + threadIdx.x;
    if (c >= N) return;

    int   pack0 = g_cntpack[0][c], pack1 = g_cntpack[1][c];
    float se0 = g_sumexp[0][c], se1 = g_sumexp[1][c];
    float pl0 = g_poslog[0][c], pl1 = g_poslog[1][c];

    int cnt0 = pack0 & 0xFFFF, pc0 = pack0 >> 16;
    int cnt1 = pack1 & 0xFFFF, pc1 = pack1 >> 16;

    float v = 0.f;
    if (cnt0 > 0 && pc0 == 1) v += (logf(se0) - pl0) / (float)cnt0;
    if (cnt1 > 0 && pc1 == 1) v += (logf(se1) - pl1) / (float)cnt1;
    g_contrib[c] = v;
}

// Gather g_contrib over idx entries (duplicates give multiplicity for free),
// clean the accumulator arrays (disjoint from what we read), reduce, publish.
__global__ void __launch_bounds__(256) reduce_kernel(
    float* __restrict__ out,
    const int* __restrict__ idx,
    int N, int K)
{
    int t = blockIdx.x * blockDim.x + threadIdx.x;

    float local = 0.f;
    if (t < K) local = g_contrib[__ldg(&idx[t])];

    if (t < N) {   // self-clean accumulators for next replay (not g_contrib)
        g_cntpack[0][t] = 0; g_cntpack[1][t] = 0;
        g_sumexp[0][t] = 0.f; g_sumexp[1][t] = 0.f;
        g_poslog[0][t] = 0.f; g_poslog[1][t] = 0.f;
    }

    #pragma unroll
    for (int s = 16; s > 0; s >>= 1)
        local += __shfl_xor_sync(0xFFFFFFFF, local, s);

    __shared__ float warpsum[8];
    int lane = threadIdx.x & 31, wid = threadIdx.x >> 5;
    if (lane == 0) warpsum[wid] = local;
    __syncthreads();
    if (wid == 0) {
        float b = (lane < 8) ? warpsum[lane] : 0.f;
        #pragma unroll
        for (int s = 4; s > 0; s >>= 1)
            b += __shfl_xor_sync(0xFFFFFFFF, b, s);
        if (lane == 0) {
            atomicAdd(&g_res, b);
            __threadfence();
            unsigned d = atomicAdd(&g_done, 1u);
            if (d == gridDim.x - 1) {
                out[0] = atomicExch(&g_res, 0.f);
                g_done = 0;
            }
        }
    }
}

extern "C" void kernel_launch(void* const* d_in, const int* in_sizes, int n_in,
                              void* d_out, int out_size) {
    const float* outs = (const float*)d_in[0];   // outputs  [N] f32
    const int*   tgt  = (const int*)d_in[1];     // targets  [N] i32
    const int*   adj  = (const int*)d_in[2];     // node_adj [N,N] i32
    const int*   idx  = (const int*)d_in[3];     // idx_node [K] i32 (sorted)
    int N = in_sizes[0];
    int K = in_sizes[3];
    float* out = (float*)d_out;

    // quadsPerRow = N/4 is a power of two; rowShift = log2(N/4)
    int rowShift = 0;
    for (int t = N >> 2; t > 1; t >>= 1) rowShift++;

    // 2048 blocks x 256 threads: stride = 2^19 divides 2^24 quads exactly
    // -> 4 uniform unrolled x8 iterations per thread, zero tail.
    main_kernel<<<2048, 256>>>((const int4*)adj, outs, tgt, N, rowShift);
    contrib_kernel<<<(N + 255) / 256, 256>>>(N);
    reduce_kernel<<<(N + 255) / 256, 256>>>(out, idx, N, K);
}